// round 8
// baseline (speedup 1.0000x reference)
#include <cuda_runtime.h>

// FFJORD: 2 chained fixed-step DOPRI5 integrations of a (64+1)->256->256->64 MLP.
// One CTA integrates 16 batch rows. fp32 via fma.rn.f32x2, zero-MOV operands
// (dup-layout activations, natural LDG.128 weight pairs).
// R8: weight stream is L2-resident (W2 doesn't fit live L1D) -> depth-16
// prefetch ring (~640 cyc cover vs 262 cyc L2 latency); launch_bounds(128,2)
// frees the register budget (R6's (128,3) pinned ptxas at 170 regs).

typedef unsigned long long u64;

#define Dd     64
#define Hh     256
#define MROWS  16
#define STRD   36      // duplicated-activation stride (floats)
#define STRH2  20      // non-dup H2 stride (floats)
#define STRY   16
#define NT     128
#define NSTEPS 16
#define NCTAS  (4096 / MROWS)   // 256
#define RD     16      // weight prefetch ring depth (covers L2 latency)

// smem: sZd[(Dd+1)][STRD] + sH1d[Hh][STRD] + sH2[Hh][STRH2] + sY[Dd][STRY]
#define SM_FLOATS ((Dd + 1 + Hh) * STRD + Hh * STRH2 + Dd * STRY)
#define SM_BYTES  (SM_FLOATS * 4)    // 70,800 B

__device__ float gK[NCTAS][6 * Dd * STRY];

struct FfjordParams {
    const float* W1[2]; const float* b1[2];
    const float* W2[2]; const float* b2[2];
    const float* W3[2]; const float* b3[2];
};

__device__ __forceinline__ u64 mk2(float lo, float hi) {
    u64 r; asm("mov.b64 %0, {%1, %2};" : "=l"(r)
               : "r"(__float_as_uint(lo)), "r"(__float_as_uint(hi)));
    return r;
}
__device__ __forceinline__ u64 dup2(float v) {
    u64 r; asm("mov.b64 %0, {%1, %1};" : "=l"(r) : "r"(__float_as_uint(v)));
    return r;
}
__device__ __forceinline__ void fma2(u64& d, u64 a, u64 b) {
    asm("fma.rn.f32x2 %0, %1, %2, %3;" : "=l"(d) : "l"(a), "l"(b), "l"(d));
}
__device__ __forceinline__ float lo32(u64 v){ return __uint_as_float((unsigned)v); }
__device__ __forceinline__ float hi32(u64 v){ return __uint_as_float((unsigned)(v>>32)); }

__device__ __forceinline__ void ldg2(u64& a, u64& b, const float* p) {
    asm("ld.global.nc.v2.u64 {%0, %1}, [%2];" : "=l"(a), "=l"(b) : "l"(p));
}
__device__ __forceinline__ u64 ldg1(const float* p) {
    u64 r; asm("ld.global.nc.u64 %0, [%1];" : "=l"(r) : "l"(p)); return r;
}

__device__ __forceinline__ float fast_tanh(float x) {
    float u = __expf(2.0f * x);
    return 1.0f - __fdividef(2.0f, u + 1.0f);
}

__constant__ float DP_A[6][5] = {
    { 0.f, 0.f, 0.f, 0.f, 0.f },
    { 1.f/5.f, 0.f, 0.f, 0.f, 0.f },
    { 3.f/40.f, 9.f/40.f, 0.f, 0.f, 0.f },
    { 44.f/45.f, -56.f/15.f, 32.f/9.f, 0.f, 0.f },
    { 19372.f/6561.f, -25360.f/2187.f, 64448.f/6561.f, -212.f/729.f, 0.f },
    { 9017.f/3168.f, -355.f/33.f, 46732.f/5247.f, 49.f/176.f, -5103.f/18656.f },
};
__constant__ float DP_C[6] = { 0.f, 1.f/5.f, 3.f/10.f, 4.f/5.f, 8.f/9.f, 1.f };

// N=256 layer. 4 warps: rowgroup rg=w&1 (rows 8*rg..+7), colgroup g=w>>1
// (cols 128*g + 4*lane..+3). DUPOUT selects duplicated vs plain output layout.
template<int K, bool TANH, bool DUPOUT>
__device__ __forceinline__ void dense256(
    const float* __restrict__ W, const float* __restrict__ bias,
    const float* __restrict__ sAd, float* __restrict__ sOut,
    int lane, int g, int r0)
{
    u64 acc[8][2];
    {
        float4 b = *(const float4*)(bias + 128*g + 4*lane);
        u64 p0 = mk2(b.x, b.y), p1 = mk2(b.z, b.w);
#pragma unroll
        for (int r = 0; r < 8; r++) { acc[r][0] = p0; acc[r][1] = p1; }
    }

    const float* w0 = W + 128*g + 4*lane;
    const float* aP = sAd + 2*r0;

    u64 wb[RD][2];                     // depth-16 weight ring (LDG.128)
#pragma unroll
    for (int s = 0; s < RD; s++) ldg2(wb[s][0], wb[s][1], w0 + s*Hh);

    u64 ab[2][8];                      // dist-1 activation dup pairs (8 rows)
#pragma unroll
    for (int q = 0; q < 4; q++) {
        ulonglong2 t = *(const ulonglong2*)(aP + 4*q);
        ab[0][2*q] = t.x; ab[0][2*q+1] = t.y;
    }

    int k = 0;
#pragma unroll 8
    for (; k < K - RD; k++) {
        const int slot = k & (RD-1), pb = k & 1;
        u64 wA = wb[slot][0], wB = wb[slot][1];
        ldg2(wb[slot][0], wb[slot][1], w0 + (k + RD)*Hh);
        {
            const float* ap1 = aP + (k+1)*STRD;
#pragma unroll
            for (int q = 0; q < 4; q++) {
                ulonglong2 t = *(const ulonglong2*)(ap1 + 4*q);
                ab[pb^1][2*q] = t.x; ab[pb^1][2*q+1] = t.y;
            }
        }
#pragma unroll
        for (int r = 0; r < 8; r++) {
            fma2(acc[r][0], ab[pb][r], wA);
            fma2(acc[r][1], ab[pb][r], wB);
        }
    }
#pragma unroll
    for (; k < K; k++) {               // tail: ring holds k..K-1
        const int slot = k & (RD-1), pb = k & 1;
        u64 wA = wb[slot][0], wB = wb[slot][1];
        if (k + 1 < K) {
            const float* ap1 = aP + (k+1)*STRD;
#pragma unroll
            for (int q = 0; q < 4; q++) {
                ulonglong2 t = *(const ulonglong2*)(ap1 + 4*q);
                ab[pb^1][2*q] = t.x; ab[pb^1][2*q+1] = t.y;
            }
        }
#pragma unroll
        for (int r = 0; r < 8; r++) {
            fma2(acc[r][0], ab[pb][r], wA);
            fma2(acc[r][1], ab[pb][r], wB);
        }
    }

#pragma unroll
    for (int p = 0; p < 2; p++) {
        int c = 128*g + 4*lane + 2*p;
        float lv[8], hv[8];
#pragma unroll
        for (int r = 0; r < 8; r++) {
            lv[r] = lo32(acc[r][p]); hv[r] = hi32(acc[r][p]);
            if (TANH) { lv[r] = fast_tanh(lv[r]); hv[r] = fast_tanh(hv[r]); }
        }
        if (DUPOUT) {
            float* o0 = sOut + c*STRD + 2*r0;
            float* o1 = sOut + (c+1)*STRD + 2*r0;
#pragma unroll
            for (int q = 0; q < 4; q++) {
                *(float4*)(o0 + 4*q) = make_float4(lv[2*q], lv[2*q], lv[2*q+1], lv[2*q+1]);
                *(float4*)(o1 + 4*q) = make_float4(hv[2*q], hv[2*q], hv[2*q+1], hv[2*q+1]);
            }
        } else {
            float* o0 = sOut + c*STRH2 + r0;
            float* o1 = sOut + (c+1)*STRH2 + r0;
            *(float4*)(o0)     = make_float4(lv[0], lv[1], lv[2], lv[3]);
            *(float4*)(o0 + 4) = make_float4(lv[4], lv[5], lv[6], lv[7]);
            *(float4*)(o1)     = make_float4(hv[0], hv[1], hv[2], hv[3]);
            *(float4*)(o1 + 4) = make_float4(hv[4], hv[5], hv[6], hv[7]);
        }
    }
}

// N=64 output layer (K=256). 4 warps: warp w -> rows 4w..4w+3;
// thread: cols (2*lane, 2*lane+1) x 4 rows. Reads NON-dup H2 (stride STRH2).
__device__ __forceinline__ void dense64out(
    const float* __restrict__ W, const float* __restrict__ bias,
    const float* __restrict__ sA, float* __restrict__ gOut,
    int lane, int r0d)
{
    u64 acc[4];
    {
        float2 bb = *(const float2*)(bias + 2*lane);
        u64 bp = mk2(bb.x, bb.y);
#pragma unroll
        for (int r = 0; r < 4; r++) acc[r] = bp;
    }
    const float* w0 = W + 2*lane;
    const float* aP = sA + r0d;

    u64 wb[RD];
#pragma unroll
    for (int s = 0; s < RD; s++) wb[s] = ldg1(w0 + s*Dd);
    float4 af[2];
    af[0] = *(const float4*)(aP);

    int k = 0;
#pragma unroll 8
    for (; k < Hh - RD; k++) {
        const int slot = k & (RD-1), pb = k & 1;
        u64 w = wb[slot];
        wb[slot] = ldg1(w0 + (k + RD)*Dd);
        float4 a4 = af[pb];
        af[pb^1] = *(const float4*)(aP + (k+1)*STRH2);
        fma2(acc[0], dup2(a4.x), w); fma2(acc[1], dup2(a4.y), w);
        fma2(acc[2], dup2(a4.z), w); fma2(acc[3], dup2(a4.w), w);
    }
#pragma unroll
    for (; k < Hh; k++) {
        const int slot = k & (RD-1), pb = k & 1;
        u64 w = wb[slot];
        float4 a4 = af[pb];
        if (k + 1 < Hh) af[pb^1] = *(const float4*)(aP + (k+1)*STRH2);
        fma2(acc[0], dup2(a4.x), w); fma2(acc[1], dup2(a4.y), w);
        fma2(acc[2], dup2(a4.z), w); fma2(acc[3], dup2(a4.w), w);
    }

    *(float4*)(gOut + (2*lane    )*STRY + r0d) =
        make_float4(lo32(acc[0]), lo32(acc[1]), lo32(acc[2]), lo32(acc[3]));
    *(float4*)(gOut + (2*lane + 1)*STRY + r0d) =
        make_float4(hi32(acc[0]), hi32(acc[1]), hi32(acc[2]), hi32(acc[3]));
}

__global__ void __launch_bounds__(NT, 2)
ffjord_kernel(const float* __restrict__ x, float* __restrict__ out, FfjordParams P)
{
    extern __shared__ float sm[];
    float* sZd  = sm;                          // (Dd+1) x STRD, duplicated
    float* sH1d = sZd + (Dd + 1) * STRD;       // Hh x STRD, duplicated
    float* sH2  = sH1d + Hh * STRD;            // Hh x STRH2, plain
    float* sY   = sH2 + Hh * STRH2;            // Dd x STRY

    const int tid   = threadIdx.x;
    const int lane  = tid & 31;
    const int w     = tid >> 5;                // 0..3
    const int r0    = (w & 1) * 8;             // dense256 rowgroup (8 rows)
    const int g     = w >> 1;                  // dense256 colgroup
    const int r0d   = w * 4;                   // dense64 rowgroup (4 rows)
    const int rbase = blockIdx.x * MROWS;
    float* gk = gK[blockIdx.x];

    for (int i = tid; i < MROWS * Dd; i += NT) {
        int r = i >> 6, d = i & 63;
        sY[d * STRY + r] = x[(rbase + r) * Dd + d];
    }
    __syncthreads();

    const float h = 1.0f / 16.0f;

    for (int bij = 0; bij < 2; bij++) {
        const float* W1 = P.W1[bij]; const float* b1 = P.b1[bij];
        const float* W2 = P.W2[bij]; const float* b2 = P.b2[bij];
        const float* W3 = P.W3[bij]; const float* b3 = P.b3[bij];

        for (int step = 0; step < NSTEPS; step++) {
            float t0 = (float)step * h;

            for (int s = 0; s < 6; s++) {
                float tstage = t0 + DP_C[s] * h;
                float ha[5];
#pragma unroll
                for (int l = 0; l < 5; l++) ha[l] = h * DP_A[s][l];

                for (int i = tid; i < (Dd + 1) * MROWS; i += NT) {
                    int d = i >> 4, r = i & 15;
                    float z;
                    if (d == Dd) {
                        z = tstage;
                    } else {
                        z = sY[d * STRY + r];
#pragma unroll
                        for (int l = 0; l < 5; l++)
                            if (l < s) z += ha[l] * gk[(l * Dd + d) * STRY + r];
                    }
                    *(float2*)(sZd + d * STRD + 2 * r) = make_float2(z, z);
                }
                __syncthreads();

                dense256<Dd + 1, true, true >(W1, b1, sZd,  sH1d, lane, g, r0);
                __syncthreads();
                dense256<Hh,     true, false>(W2, b2, sH1d, sH2,  lane, g, r0);
                __syncthreads();
                dense64out(W3, b3, sH2, gk + s * Dd * STRY, lane, r0d);
                __syncthreads();
            }

            for (int i = tid; i < Dd * MROWS; i += NT) {
                int d = i >> 4, r = i & 15;
                int o = d * STRY + r;
                float acc = (35.f/384.f)     * gk[o]
                          + (500.f/1113.f)   * gk[(2*Dd)*STRY + o]
                          + (125.f/192.f)    * gk[(3*Dd)*STRY + o]
                          + (-2187.f/6784.f) * gk[(4*Dd)*STRY + o]
                          + (11.f/84.f)      * gk[(5*Dd)*STRY + o];
                sY[o] += h * acc;
            }
            __syncthreads();
        }
    }

    for (int i = tid; i < MROWS * Dd; i += NT) {
        int r = i >> 6, d = i & 63;
        out[(rbase + r) * Dd + d] = sY[d * STRY + r];
    }
}

extern "C" void kernel_launch(void* const* d_in, const int* in_sizes, int n_in,
                              void* d_out, int out_size)
{
    (void)in_sizes; (void)n_in; (void)out_size;
    const float* x = (const float*)d_in[0];

    FfjordParams P;
    P.W1[0] = (const float*)d_in[1];  P.b1[0] = (const float*)d_in[2];
    P.W2[0] = (const float*)d_in[3];  P.b2[0] = (const float*)d_in[4];
    P.W3[0] = (const float*)d_in[5];  P.b3[0] = (const float*)d_in[6];
    P.W1[1] = (const float*)d_in[7];  P.b1[1] = (const float*)d_in[8];
    P.W2[1] = (const float*)d_in[9];  P.b2[1] = (const float*)d_in[10];
    P.W3[1] = (const float*)d_in[11]; P.b3[1] = (const float*)d_in[12];

    static_assert(SM_BYTES <= 100 * 1024, "smem budget");
    cudaFuncSetAttribute(ffjord_kernel, cudaFuncAttributeMaxDynamicSharedMemorySize, SM_BYTES);

    ffjord_kernel<<<NCTAS, NT, SM_BYTES>>>(x, (float*)d_out, P);
}

// round 9
// speedup vs baseline: 1.9124x; 1.9124x over previous
#include <cuda_runtime.h>

// FFJORD: 2 chained fixed-step DOPRI5 integrations of a (64+1)->256->256->64 MLP.
// One CTA integrates 16 batch rows. fp32 via fma.rn.f32x2, zero-MOV operands.
// R9 = R6 base (best known) + : RD=8 (R8's RD=16 spilled), launch_bounds(128,2),
// RK stage buffer sK back in smem (no gK L2 round-trips), and bank-conflict
// staggering of epilogue stores (rotate store order per lane).

typedef unsigned long long u64;

#define Dd     64
#define Hh     256
#define MROWS  16
#define STRD   36      // duplicated-activation stride (floats)
#define STRH2  20      // non-dup H2 stride (floats)
#define STRY   16      // sY stride
#define STRK   20      // sK stride (floats)
#define NT     128
#define NSTEPS 16
#define NCTAS  (4096 / MROWS)   // 256
#define RD     8       // weight prefetch ring depth (RD=16 spills!)

// smem: sZd[(Dd+1)][STRD] + sH1d[Hh][STRD] + sH2[Hh][STRH2] + sY[Dd][STRY] + sK[6][Dd][STRK]
#define SM_FLOATS ((Dd + 1 + Hh) * STRD + Hh * STRH2 + Dd * STRY + 6 * Dd * STRK)
#define SM_BYTES  (SM_FLOATS * 4)    // 101,520 B -> 2 CTAs/SM

struct FfjordParams {
    const float* W1[2]; const float* b1[2];
    const float* W2[2]; const float* b2[2];
    const float* W3[2]; const float* b3[2];
};

__device__ __forceinline__ u64 mk2(float lo, float hi) {
    u64 r; asm("mov.b64 %0, {%1, %2};" : "=l"(r)
               : "r"(__float_as_uint(lo)), "r"(__float_as_uint(hi)));
    return r;
}
__device__ __forceinline__ u64 dup2(float v) {
    u64 r; asm("mov.b64 %0, {%1, %1};" : "=l"(r) : "r"(__float_as_uint(v)));
    return r;
}
__device__ __forceinline__ void fma2(u64& d, u64 a, u64 b) {
    asm("fma.rn.f32x2 %0, %1, %2, %3;" : "=l"(d) : "l"(a), "l"(b), "l"(d));
}
__device__ __forceinline__ float lo32(u64 v){ return __uint_as_float((unsigned)v); }
__device__ __forceinline__ float hi32(u64 v){ return __uint_as_float((unsigned)(v>>32)); }

__device__ __forceinline__ void ldg2(u64& a, u64& b, const float* p) {
    asm("ld.global.nc.v2.u64 {%0, %1}, [%2];" : "=l"(a), "=l"(b) : "l"(p));
}
__device__ __forceinline__ u64 ldg1(const float* p) {
    u64 r; asm("ld.global.nc.u64 %0, [%1];" : "=l"(r) : "l"(p)); return r;
}

__device__ __forceinline__ float fast_tanh(float x) {
    float u = __expf(2.0f * x);
    return 1.0f - __fdividef(2.0f, u + 1.0f);
}

__constant__ float DP_A[6][5] = {
    { 0.f, 0.f, 0.f, 0.f, 0.f },
    { 1.f/5.f, 0.f, 0.f, 0.f, 0.f },
    { 3.f/40.f, 9.f/40.f, 0.f, 0.f, 0.f },
    { 44.f/45.f, -56.f/15.f, 32.f/9.f, 0.f, 0.f },
    { 19372.f/6561.f, -25360.f/2187.f, 64448.f/6561.f, -212.f/729.f, 0.f },
    { 9017.f/3168.f, -355.f/33.f, 46732.f/5247.f, 49.f/176.f, -5103.f/18656.f },
};
__constant__ float DP_C[6] = { 0.f, 1.f/5.f, 3.f/10.f, 4.f/5.f, 8.f/9.f, 1.f };

// N=256 layer. 4 warps: rowgroup rg=w&1 (rows 8*rg..+7), colgroup g=w>>1
// (cols 128*g + 4*lane..+3). DUPOUT selects duplicated vs plain output layout.
// Epilogue stores rotated by lane to cut bank-conflict degree.
template<int K, bool TANH, bool DUPOUT>
__device__ __forceinline__ void dense256(
    const float* __restrict__ W, const float* __restrict__ bias,
    const float* __restrict__ sAd, float* __restrict__ sOut,
    int lane, int g, int r0)
{
    u64 acc[8][2];
    {
        float4 b = *(const float4*)(bias + 128*g + 4*lane);
        u64 p0 = mk2(b.x, b.y), p1 = mk2(b.z, b.w);
#pragma unroll
        for (int r = 0; r < 8; r++) { acc[r][0] = p0; acc[r][1] = p1; }
    }

    const float* w0 = W + 128*g + 4*lane;
    const float* aP = sAd + 2*r0;

    u64 wb[RD][2];                     // depth-8 weight ring (LDG.128)
#pragma unroll
    for (int s = 0; s < RD; s++) ldg2(wb[s][0], wb[s][1], w0 + s*Hh);

    u64 ab[2][8];                      // dist-1 activation dup pairs (8 rows)
#pragma unroll
    for (int q = 0; q < 4; q++) {
        ulonglong2 t = *(const ulonglong2*)(aP + 4*q);
        ab[0][2*q] = t.x; ab[0][2*q+1] = t.y;
    }

    int k = 0;
#pragma unroll 8
    for (; k < K - RD; k++) {
        const int slot = k & (RD-1), pb = k & 1;
        u64 wA = wb[slot][0], wB = wb[slot][1];
        ldg2(wb[slot][0], wb[slot][1], w0 + (k + RD)*Hh);
        {
            const float* ap1 = aP + (k+1)*STRD;
#pragma unroll
            for (int q = 0; q < 4; q++) {
                ulonglong2 t = *(const ulonglong2*)(ap1 + 4*q);
                ab[pb^1][2*q] = t.x; ab[pb^1][2*q+1] = t.y;
            }
        }
#pragma unroll
        for (int r = 0; r < 8; r++) {
            fma2(acc[r][0], ab[pb][r], wA);
            fma2(acc[r][1], ab[pb][r], wB);
        }
    }
#pragma unroll
    for (; k < K; k++) {               // tail: ring holds k..K-1
        const int slot = k & (RD-1), pb = k & 1;
        u64 wA = wb[slot][0], wB = wb[slot][1];
        if (k + 1 < K) {
            const float* ap1 = aP + (k+1)*STRD;
#pragma unroll
            for (int q = 0; q < 4; q++) {
                ulonglong2 t = *(const ulonglong2*)(ap1 + 4*q);
                ab[pb^1][2*q] = t.x; ab[pb^1][2*q+1] = t.y;
            }
        }
#pragma unroll
        for (int r = 0; r < 8; r++) {
            fma2(acc[r][0], ab[pb][r], wA);
            fma2(acc[r][1], ab[pb][r], wB);
        }
    }

    const int rot = (lane >> 1) & 3;   // stagger stores across 4-bank slices
#pragma unroll
    for (int p = 0; p < 2; p++) {
        int c = 128*g + 4*lane + 2*p;
        float lv[8], hv[8];
#pragma unroll
        for (int r = 0; r < 8; r++) {
            lv[r] = lo32(acc[r][p]); hv[r] = hi32(acc[r][p]);
            if (TANH) { lv[r] = fast_tanh(lv[r]); hv[r] = fast_tanh(hv[r]); }
        }
        if (DUPOUT) {
            float* o0 = sOut + c*STRD + 2*r0;
            float* o1 = sOut + (c+1)*STRD + 2*r0;
#pragma unroll
            for (int qq = 0; qq < 4; qq++) {
                int q = (qq + rot) & 3;
                *(float4*)(o0 + 4*q) = make_float4(lv[2*q], lv[2*q], lv[2*q+1], lv[2*q+1]);
                *(float4*)(o1 + 4*q) = make_float4(hv[2*q], hv[2*q], hv[2*q+1], hv[2*q+1]);
            }
        } else {
            float* o0 = sOut + c*STRH2 + r0;
            float* o1 = sOut + (c+1)*STRH2 + r0;
            float4 vv[4] = {
                make_float4(lv[0], lv[1], lv[2], lv[3]),
                make_float4(lv[4], lv[5], lv[6], lv[7]),
                make_float4(hv[0], hv[1], hv[2], hv[3]),
                make_float4(hv[4], hv[5], hv[6], hv[7])
            };
            float* pp[4] = { o0, o0 + 4, o1, o1 + 4 };
#pragma unroll
            for (int jj = 0; jj < 4; jj++) {
                int j = (jj + rot) & 3;
                *(float4*)pp[j] = vv[j];
            }
        }
    }
}

// N=64 output layer (K=256). 4 warps: warp w -> rows 4w..4w+3;
// thread: cols (2*lane, 2*lane+1) x 4 rows. Reads NON-dup H2; writes smem sK
// (stride STRK) with pair-swapped store order.
__device__ __forceinline__ void dense64out(
    const float* __restrict__ W, const float* __restrict__ bias,
    const float* __restrict__ sA, float* __restrict__ sKs,
    int lane, int r0d)
{
    u64 acc[4];
    {
        float2 bb = *(const float2*)(bias + 2*lane);
        u64 bp = mk2(bb.x, bb.y);
#pragma unroll
        for (int r = 0; r < 4; r++) acc[r] = bp;
    }
    const float* w0 = W + 2*lane;
    const float* aP = sA + r0d;

    u64 wb[RD];
#pragma unroll
    for (int s = 0; s < RD; s++) wb[s] = ldg1(w0 + s*Dd);
    float4 af[2];
    af[0] = *(const float4*)(aP);

    int k = 0;
#pragma unroll 8
    for (; k < Hh - RD; k++) {
        const int slot = k & (RD-1), pb = k & 1;
        u64 w = wb[slot];
        wb[slot] = ldg1(w0 + (k + RD)*Dd);
        float4 a4 = af[pb];
        af[pb^1] = *(const float4*)(aP + (k+1)*STRH2);
        fma2(acc[0], dup2(a4.x), w); fma2(acc[1], dup2(a4.y), w);
        fma2(acc[2], dup2(a4.z), w); fma2(acc[3], dup2(a4.w), w);
    }
#pragma unroll
    for (; k < Hh; k++) {
        const int slot = k & (RD-1), pb = k & 1;
        u64 w = wb[slot];
        float4 a4 = af[pb];
        if (k + 1 < Hh) af[pb^1] = *(const float4*)(aP + (k+1)*STRH2);
        fma2(acc[0], dup2(a4.x), w); fma2(acc[1], dup2(a4.y), w);
        fma2(acc[2], dup2(a4.z), w); fma2(acc[3], dup2(a4.w), w);
    }

    float* p0 = sKs + (2*lane    )*STRK + r0d;
    float* p1 = sKs + (2*lane + 1)*STRK + r0d;
    float4 v0 = make_float4(lo32(acc[0]), lo32(acc[1]), lo32(acc[2]), lo32(acc[3]));
    float4 v1 = make_float4(hi32(acc[0]), hi32(acc[1]), hi32(acc[2]), hi32(acc[3]));
    if ((lane >> 1) & 1) {
        *(float4*)p1 = v1; *(float4*)p0 = v0;
    } else {
        *(float4*)p0 = v0; *(float4*)p1 = v1;
    }
}

__global__ void __launch_bounds__(NT, 2)
ffjord_kernel(const float* __restrict__ x, float* __restrict__ out, FfjordParams P)
{
    extern __shared__ float sm[];
    float* sZd  = sm;                          // (Dd+1) x STRD, duplicated
    float* sH1d = sZd + (Dd + 1) * STRD;       // Hh x STRD, duplicated
    float* sH2  = sH1d + Hh * STRD;            // Hh x STRH2, plain
    float* sY   = sH2 + Hh * STRH2;            // Dd x STRY
    float* sK   = sY + Dd * STRY;              // [6][Dd][STRK]

    const int tid   = threadIdx.x;
    const int lane  = tid & 31;
    const int w     = tid >> 5;                // 0..3
    const int r0    = (w & 1) * 8;             // dense256 rowgroup (8 rows)
    const int g     = w >> 1;                  // dense256 colgroup
    const int r0d   = w * 4;                   // dense64 rowgroup (4 rows)
    const int rbase = blockIdx.x * MROWS;

    for (int i = tid; i < MROWS * Dd; i += NT) {
        int r = i >> 6, d = i & 63;
        sY[d * STRY + r] = x[(rbase + r) * Dd + d];
    }
    __syncthreads();

    const float h = 1.0f / 16.0f;

    for (int bij = 0; bij < 2; bij++) {
        const float* W1 = P.W1[bij]; const float* b1 = P.b1[bij];
        const float* W2 = P.W2[bij]; const float* b2 = P.b2[bij];
        const float* W3 = P.W3[bij]; const float* b3 = P.b3[bij];

        for (int step = 0; step < NSTEPS; step++) {
            float t0 = (float)step * h;

            for (int s = 0; s < 6; s++) {
                float tstage = t0 + DP_C[s] * h;
                float ha[5];
#pragma unroll
                for (int l = 0; l < 5; l++) ha[l] = h * DP_A[s][l];

                for (int i = tid; i < (Dd + 1) * MROWS; i += NT) {
                    int d = i >> 4, r = i & 15;
                    float z;
                    if (d == Dd) {
                        z = tstage;
                    } else {
                        z = sY[d * STRY + r];
#pragma unroll
                        for (int l = 0; l < 5; l++)
                            if (l < s) z += ha[l] * sK[(l * Dd + d) * STRK + r];
                    }
                    *(float2*)(sZd + d * STRD + 2 * r) = make_float2(z, z);
                }
                __syncthreads();

                dense256<Dd + 1, true, true >(W1, b1, sZd,  sH1d, lane, g, r0);
                __syncthreads();
                dense256<Hh,     true, false>(W2, b2, sH1d, sH2,  lane, g, r0);
                __syncthreads();
                dense64out(W3, b3, sH2, sK + s * Dd * STRK, lane, r0d);
                __syncthreads();
            }

            for (int i = tid; i < Dd * MROWS; i += NT) {
                int d = i >> 4, r = i & 15;
                int ok = d * STRK + r;
                float acc = (35.f/384.f)     * sK[ok]
                          + (500.f/1113.f)   * sK[(2*Dd)*STRK + ok]
                          + (125.f/192.f)    * sK[(3*Dd)*STRK + ok]
                          + (-2187.f/6784.f) * sK[(4*Dd)*STRK + ok]
                          + (11.f/84.f)      * sK[(5*Dd)*STRK + ok];
                sY[d * STRY + r] += h * acc;
            }
            __syncthreads();
        }
    }

    for (int i = tid; i < MROWS * Dd; i += NT) {
        int r = i >> 6, d = i & 63;
        out[(rbase + r) * Dd + d] = sY[d * STRY + r];
    }
}

extern "C" void kernel_launch(void* const* d_in, const int* in_sizes, int n_in,
                              void* d_out, int out_size)
{
    (void)in_sizes; (void)n_in; (void)out_size;
    const float* x = (const float*)d_in[0];

    FfjordParams P;
    P.W1[0] = (const float*)d_in[1];  P.b1[0] = (const float*)d_in[2];
    P.W2[0] = (const float*)d_in[3];  P.b2[0] = (const float*)d_in[4];
    P.W3[0] = (const float*)d_in[5];  P.b3[0] = (const float*)d_in[6];
    P.W1[1] = (const float*)d_in[7];  P.b1[1] = (const float*)d_in[8];
    P.W2[1] = (const float*)d_in[9];  P.b2[1] = (const float*)d_in[10];
    P.W3[1] = (const float*)d_in[11]; P.b3[1] = (const float*)d_in[12];

    static_assert(SM_BYTES <= 104 * 1024, "smem budget (2 CTAs/SM)");
    cudaFuncSetAttribute(ffjord_kernel, cudaFuncAttributeMaxDynamicSharedMemorySize, SM_BYTES);

    ffjord_kernel<<<NCTAS, NT, SM_BYTES>>>(x, (float*)d_out, P);
}

// round 10
// speedup vs baseline: 2.0975x; 1.0968x over previous
#include <cuda_runtime.h>

// FFJORD: 2 chained fixed-step DOPRI5 integrations of a (64+1)->256->256->64 MLP.
// One CTA integrates 16 batch rows. fp32 via fma.rn.f32x2.
// R10: de-dup activations (plain stride-20 layout) — 2 LDS.128 + 8 dup2 movs
// per k instead of 4 LDS.128. L1 wavefronts/k-round drop 64->48 (< 64 FMA cyc),
// making the FMA pipe the sole binding resource. smem 81KB; RD=8; sK in smem.

typedef unsigned long long u64;

#define Dd     64
#define Hh     256
#define MROWS  16
#define STRA   20      // plain activation stride (floats, 80B rows, 16B-aligned)
#define STRY   16
#define NT     128
#define NSTEPS 16
#define NCTAS  (4096 / MROWS)   // 256
#define RD     8       // weight prefetch ring depth (16 spills, 4 exposes L2)

// smem: sZ[(Dd+1)][STRA] + sH1[Hh][STRA] + sH2[Hh][STRA] + sY[Dd][STRY] + sK[6][Dd][STRA]
#define SM_FLOATS ((Dd + 1 + Hh + Hh + 6*Dd) * STRA + Dd * STRY)
#define SM_BYTES  (SM_FLOATS * 4)    // 80,976 B -> 2 CTAs/SM, ~66KB live L1D

struct FfjordParams {
    const float* W1[2]; const float* b1[2];
    const float* W2[2]; const float* b2[2];
    const float* W3[2]; const float* b3[2];
};

__device__ __forceinline__ u64 mk2(float lo, float hi) {
    u64 r; asm("mov.b64 %0, {%1, %2};" : "=l"(r)
               : "r"(__float_as_uint(lo)), "r"(__float_as_uint(hi)));
    return r;
}
__device__ __forceinline__ u64 dup2(float v) {
    u64 r; asm("mov.b64 %0, {%1, %1};" : "=l"(r) : "r"(__float_as_uint(v)));
    return r;
}
__device__ __forceinline__ void fma2(u64& d, u64 a, u64 b) {
    asm("fma.rn.f32x2 %0, %1, %2, %3;" : "=l"(d) : "l"(a), "l"(b), "l"(d));
}
__device__ __forceinline__ float lo32(u64 v){ return __uint_as_float((unsigned)v); }
__device__ __forceinline__ float hi32(u64 v){ return __uint_as_float((unsigned)(v>>32)); }

__device__ __forceinline__ void ldg2(u64& a, u64& b, const float* p) {
    asm("ld.global.nc.v2.u64 {%0, %1}, [%2];" : "=l"(a), "=l"(b) : "l"(p));
}
__device__ __forceinline__ u64 ldg1(const float* p) {
    u64 r; asm("ld.global.nc.u64 %0, [%1];" : "=l"(r) : "l"(p)); return r;
}

__device__ __forceinline__ float fast_tanh(float x) {
    float u = __expf(2.0f * x);
    return 1.0f - __fdividef(2.0f, u + 1.0f);
}

__constant__ float DP_A[6][5] = {
    { 0.f, 0.f, 0.f, 0.f, 0.f },
    { 1.f/5.f, 0.f, 0.f, 0.f, 0.f },
    { 3.f/40.f, 9.f/40.f, 0.f, 0.f, 0.f },
    { 44.f/45.f, -56.f/15.f, 32.f/9.f, 0.f, 0.f },
    { 19372.f/6561.f, -25360.f/2187.f, 64448.f/6561.f, -212.f/729.f, 0.f },
    { 9017.f/3168.f, -355.f/33.f, 46732.f/5247.f, 49.f/176.f, -5103.f/18656.f },
};
__constant__ float DP_C[6] = { 0.f, 1.f/5.f, 3.f/10.f, 4.f/5.f, 8.f/9.f, 1.f };

// N=256 layer. 4 warps: rowgroup rg=w&1 (rows 8*rg..+7), colgroup g=w>>1
// (cols 128*g + 4*lane..+3). Plain activation layout in and out (stride STRA).
template<int K, bool TANH>
__device__ __forceinline__ void dense256(
    const float* __restrict__ W, const float* __restrict__ bias,
    const float* __restrict__ sA, float* __restrict__ sOut,
    int lane, int g, int r0)
{
    u64 acc[8][2];
    {
        float4 b = *(const float4*)(bias + 128*g + 4*lane);
        u64 p0 = mk2(b.x, b.y), p1 = mk2(b.z, b.w);
#pragma unroll
        for (int r = 0; r < 8; r++) { acc[r][0] = p0; acc[r][1] = p1; }
    }

    const float* w0 = W + 128*g + 4*lane;
    const float* aP = sA + r0;

    u64 wb[RD][2];                     // depth-8 weight ring (LDG.128 each)
#pragma unroll
    for (int s = 0; s < RD; s++) ldg2(wb[s][0], wb[s][1], w0 + s*Hh);

    float4 af[2][2];                   // dist-1 act prefetch: 8 rows = 2 float4
    af[0][0] = *(const float4*)(aP);
    af[0][1] = *(const float4*)(aP + 4);

    int k = 0;
#pragma unroll 8
    for (; k < K - RD; k++) {
        const int slot = k & (RD-1), pb = k & 1;
        u64 wA = wb[slot][0], wB = wb[slot][1];
        ldg2(wb[slot][0], wb[slot][1], w0 + (k + RD)*Hh);
        float4 f0 = af[pb][0], f1 = af[pb][1];
        {
            const float* ap1 = aP + (k+1)*STRA;
            af[pb^1][0] = *(const float4*)(ap1);
            af[pb^1][1] = *(const float4*)(ap1 + 4);
        }
        u64 a0 = dup2(f0.x), a1 = dup2(f0.y), a2 = dup2(f0.z), a3 = dup2(f0.w);
        u64 a4 = dup2(f1.x), a5 = dup2(f1.y), a6 = dup2(f1.z), a7 = dup2(f1.w);
        fma2(acc[0][0], a0, wA); fma2(acc[0][1], a0, wB);
        fma2(acc[1][0], a1, wA); fma2(acc[1][1], a1, wB);
        fma2(acc[2][0], a2, wA); fma2(acc[2][1], a2, wB);
        fma2(acc[3][0], a3, wA); fma2(acc[3][1], a3, wB);
        fma2(acc[4][0], a4, wA); fma2(acc[4][1], a4, wB);
        fma2(acc[5][0], a5, wA); fma2(acc[5][1], a5, wB);
        fma2(acc[6][0], a6, wA); fma2(acc[6][1], a6, wB);
        fma2(acc[7][0], a7, wA); fma2(acc[7][1], a7, wB);
    }
#pragma unroll
    for (; k < K; k++) {               // tail: ring holds k..K-1
        const int slot = k & (RD-1), pb = k & 1;
        u64 wA = wb[slot][0], wB = wb[slot][1];
        float4 f0 = af[pb][0], f1 = af[pb][1];
        if (k + 1 < K) {
            const float* ap1 = aP + (k+1)*STRA;
            af[pb^1][0] = *(const float4*)(ap1);
            af[pb^1][1] = *(const float4*)(ap1 + 4);
        }
        u64 a0 = dup2(f0.x), a1 = dup2(f0.y), a2 = dup2(f0.z), a3 = dup2(f0.w);
        u64 a4 = dup2(f1.x), a5 = dup2(f1.y), a6 = dup2(f1.z), a7 = dup2(f1.w);
        fma2(acc[0][0], a0, wA); fma2(acc[0][1], a0, wB);
        fma2(acc[1][0], a1, wA); fma2(acc[1][1], a1, wB);
        fma2(acc[2][0], a2, wA); fma2(acc[2][1], a2, wB);
        fma2(acc[3][0], a3, wA); fma2(acc[3][1], a3, wB);
        fma2(acc[4][0], a4, wA); fma2(acc[4][1], a4, wB);
        fma2(acc[5][0], a5, wA); fma2(acc[5][1], a5, wB);
        fma2(acc[6][0], a6, wA); fma2(acc[6][1], a6, wB);
        fma2(acc[7][0], a7, wA); fma2(acc[7][1], a7, wB);
    }

    const int rot = (lane >> 1) & 3;   // stagger stores across bank slices
#pragma unroll
    for (int p = 0; p < 2; p++) {
        int c = 128*g + 4*lane + 2*p;
        float lv[8], hv[8];
#pragma unroll
        for (int r = 0; r < 8; r++) {
            lv[r] = lo32(acc[r][p]); hv[r] = hi32(acc[r][p]);
            if (TANH) { lv[r] = fast_tanh(lv[r]); hv[r] = fast_tanh(hv[r]); }
        }
        float* o0 = sOut + c*STRA + r0;
        float* o1 = sOut + (c+1)*STRA + r0;
        float4 vv[4] = {
            make_float4(lv[0], lv[1], lv[2], lv[3]),
            make_float4(lv[4], lv[5], lv[6], lv[7]),
            make_float4(hv[0], hv[1], hv[2], hv[3]),
            make_float4(hv[4], hv[5], hv[6], hv[7])
        };
        float* pp[4] = { o0, o0 + 4, o1, o1 + 4 };
#pragma unroll
        for (int jj = 0; jj < 4; jj++) {
            int j = (jj + rot) & 3;
            *(float4*)pp[j] = vv[j];
        }
    }
}

// N=64 output layer (K=256). 4 warps: warp w -> rows 4w..4w+3;
// thread: cols (2*lane, 2*lane+1) x 4 rows. Plain layout (stride STRA).
__device__ __forceinline__ void dense64out(
    const float* __restrict__ W, const float* __restrict__ bias,
    const float* __restrict__ sA, float* __restrict__ sKs,
    int lane, int r0d)
{
    u64 acc[4];
    {
        float2 bb = *(const float2*)(bias + 2*lane);
        u64 bp = mk2(bb.x, bb.y);
#pragma unroll
        for (int r = 0; r < 4; r++) acc[r] = bp;
    }
    const float* w0 = W + 2*lane;
    const float* aP = sA + r0d;

    u64 wb[RD];
#pragma unroll
    for (int s = 0; s < RD; s++) wb[s] = ldg1(w0 + s*Dd);
    float4 af[2];
    af[0] = *(const float4*)(aP);

    int k = 0;
#pragma unroll 8
    for (; k < Hh - RD; k++) {
        const int slot = k & (RD-1), pb = k & 1;
        u64 w = wb[slot];
        wb[slot] = ldg1(w0 + (k + RD)*Dd);
        float4 a4 = af[pb];
        af[pb^1] = *(const float4*)(aP + (k+1)*STRA);
        fma2(acc[0], dup2(a4.x), w); fma2(acc[1], dup2(a4.y), w);
        fma2(acc[2], dup2(a4.z), w); fma2(acc[3], dup2(a4.w), w);
    }
#pragma unroll
    for (; k < Hh; k++) {
        const int slot = k & (RD-1), pb = k & 1;
        u64 w = wb[slot];
        float4 a4 = af[pb];
        if (k + 1 < Hh) af[pb^1] = *(const float4*)(aP + (k+1)*STRA);
        fma2(acc[0], dup2(a4.x), w); fma2(acc[1], dup2(a4.y), w);
        fma2(acc[2], dup2(a4.z), w); fma2(acc[3], dup2(a4.w), w);
    }

    float* p0 = sKs + (2*lane    )*STRA + r0d;
    float* p1 = sKs + (2*lane + 1)*STRA + r0d;
    float4 v0 = make_float4(lo32(acc[0]), lo32(acc[1]), lo32(acc[2]), lo32(acc[3]));
    float4 v1 = make_float4(hi32(acc[0]), hi32(acc[1]), hi32(acc[2]), hi32(acc[3]));
    if ((lane >> 1) & 1) {
        *(float4*)p1 = v1; *(float4*)p0 = v0;
    } else {
        *(float4*)p0 = v0; *(float4*)p1 = v1;
    }
}

__global__ void __launch_bounds__(NT, 2)
ffjord_kernel(const float* __restrict__ x, float* __restrict__ out, FfjordParams P)
{
    extern __shared__ float sm[];
    float* sZ   = sm;                          // (Dd+1) x STRA, plain
    float* sH1  = sZ + (Dd + 1) * STRA;        // Hh x STRA, plain
    float* sH2  = sH1 + Hh * STRA;             // Hh x STRA, plain
    float* sY   = sH2 + Hh * STRA;             // Dd x STRY
    float* sK   = sY + Dd * STRY;              // [6][Dd][STRA]

    const int tid   = threadIdx.x;
    const int lane  = tid & 31;
    const int w     = tid >> 5;                // 0..3
    const int r0    = (w & 1) * 8;             // dense256 rowgroup (8 rows)
    const int g     = w >> 1;                  // dense256 colgroup
    const int r0d   = w * 4;                   // dense64 rowgroup (4 rows)
    const int rbase = blockIdx.x * MROWS;

    for (int i = tid; i < MROWS * Dd; i += NT) {
        int r = i >> 6, d = i & 63;
        sY[d * STRY + r] = x[(rbase + r) * Dd + d];
    }
    __syncthreads();

    const float h = 1.0f / 16.0f;

    for (int bij = 0; bij < 2; bij++) {
        const float* W1 = P.W1[bij]; const float* b1 = P.b1[bij];
        const float* W2 = P.W2[bij]; const float* b2 = P.b2[bij];
        const float* W3 = P.W3[bij]; const float* b3 = P.b3[bij];

        for (int step = 0; step < NSTEPS; step++) {
            float t0 = (float)step * h;

            for (int s = 0; s < 6; s++) {
                float tstage = t0 + DP_C[s] * h;
                float ha[5];
#pragma unroll
                for (int l = 0; l < 5; l++) ha[l] = h * DP_A[s][l];

                for (int i = tid; i < (Dd + 1) * MROWS; i += NT) {
                    int d = i >> 4, r = i & 15;
                    float z;
                    if (d == Dd) {
                        z = tstage;
                    } else {
                        z = sY[d * STRY + r];
#pragma unroll
                        for (int l = 0; l < 5; l++)
                            if (l < s) z += ha[l] * sK[(l * Dd + d) * STRA + r];
                    }
                    sZ[d * STRA + r] = z;
                }
                __syncthreads();

                dense256<Dd + 1, true>(W1, b1, sZ,  sH1, lane, g, r0);
                __syncthreads();
                dense256<Hh,     true>(W2, b2, sH1, sH2, lane, g, r0);
                __syncthreads();
                dense64out(W3, b3, sH2, sK + s * Dd * STRA, lane, r0d);
                __syncthreads();
            }

            for (int i = tid; i < Dd * MROWS; i += NT) {
                int d = i >> 4, r = i & 15;
                int ok = d * STRA + r;
                float acc = (35.f/384.f)     * sK[ok]
                          + (500.f/1113.f)   * sK[(2*Dd)*STRA + ok]
                          + (125.f/192.f)    * sK[(3*Dd)*STRA + ok]
                          + (-2187.f/6784.f) * sK[(4*Dd)*STRA + ok]
                          + (11.f/84.f)      * sK[(5*Dd)*STRA + ok];
                sY[d * STRY + r] += h * acc;
            }
            __syncthreads();
        }
    }

    for (int i = tid; i < MROWS * Dd; i += NT) {
        int r = i >> 6, d = i & 63;
        out[(rbase + r) * Dd + d] = sY[d * STRY + r];
    }
}

extern "C" void kernel_launch(void* const* d_in, const int* in_sizes, int n_in,
                              void* d_out, int out_size)
{
    (void)in_sizes; (void)n_in; (void)out_size;
    const float* x = (const float*)d_in[0];

    FfjordParams P;
    P.W1[0] = (const float*)d_in[1];  P.b1[0] = (const float*)d_in[2];
    P.W2[0] = (const float*)d_in[3];  P.b2[0] = (const float*)d_in[4];
    P.W3[0] = (const float*)d_in[5];  P.b3[0] = (const float*)d_in[6];
    P.W1[1] = (const float*)d_in[7];  P.b1[1] = (const float*)d_in[8];
    P.W2[1] = (const float*)d_in[9];  P.b2[1] = (const float*)d_in[10];
    P.W3[1] = (const float*)d_in[11]; P.b3[1] = (const float*)d_in[12];

    static_assert(SM_BYTES <= 100 * 1024, "smem budget (2 CTAs/SM)");
    cudaFuncSetAttribute(ffjord_kernel, cudaFuncAttributeMaxDynamicSharedMemorySize, SM_BYTES);

    ffjord_kernel<<<NCTAS, NT, SM_BYTES>>>(x, (float*)d_out, P);
}

// round 11
// speedup vs baseline: 2.1205x; 1.0110x over previous
#include <cuda_runtime.h>

// FFJORD: 2 chained fixed-step DOPRI5 integrations of a (64+1)->256->256->64 MLP.
// One CTA integrates 16 batch rows. fp32 via fma.rn.f32x2.
// R11: row-pair accumulators — activation ulonglong2 LDS yields NATURAL (r,r+1)
// pairs (zero movs); only 4 weight dup2 movs per k. Instrs/k: 33 -> ~26,
// issue demand/SMSP 1.03 -> 0.81 IPC, freeing the FMA pipe.

typedef unsigned long long u64;

#define Dd     64
#define Hh     256
#define MROWS  16
#define STRA   20      // plain activation stride (floats, 80B rows)
#define STRY   16
#define NT     128
#define NSTEPS 16
#define NCTAS  (4096 / MROWS)   // 256
#define RD     8       // weight prefetch ring depth

// smem: sZ[(Dd+1)][STRA] + sH1[Hh][STRA] + sH2[Hh][STRA] + sY[Dd][STRY] + sK[6][Dd][STRA]
#define SM_FLOATS ((Dd + 1 + Hh + Hh + 6*Dd) * STRA + Dd * STRY)
#define SM_BYTES  (SM_FLOATS * 4)    // 80,976 B -> 2 CTAs/SM

struct FfjordParams {
    const float* W1[2]; const float* b1[2];
    const float* W2[2]; const float* b2[2];
    const float* W3[2]; const float* b3[2];
};

__device__ __forceinline__ u64 dup2(float v) {
    u64 r; asm("mov.b64 %0, {%1, %1};" : "=l"(r) : "r"(__float_as_uint(v)));
    return r;
}
__device__ __forceinline__ void fma2(u64& d, u64 a, u64 b) {
    asm("fma.rn.f32x2 %0, %1, %2, %3;" : "=l"(d) : "l"(a), "l"(b), "l"(d));
}
__device__ __forceinline__ float lo32(u64 v){ return __uint_as_float((unsigned)v); }
__device__ __forceinline__ float hi32(u64 v){ return __uint_as_float((unsigned)(v>>32)); }

__device__ __forceinline__ float4 ldg4(const float* p) {
    float4 v;
    asm("ld.global.nc.v4.f32 {%0,%1,%2,%3}, [%4];"
        : "=f"(v.x), "=f"(v.y), "=f"(v.z), "=f"(v.w) : "l"(p));
    return v;
}
__device__ __forceinline__ float2 ldg2f(const float* p) {
    float2 v;
    asm("ld.global.nc.v2.f32 {%0,%1}, [%2];" : "=f"(v.x), "=f"(v.y) : "l"(p));
    return v;
}

__device__ __forceinline__ float fast_tanh(float x) {
    float u = __expf(2.0f * x);
    return 1.0f - __fdividef(2.0f, u + 1.0f);
}

__constant__ float DP_A[6][5] = {
    { 0.f, 0.f, 0.f, 0.f, 0.f },
    { 1.f/5.f, 0.f, 0.f, 0.f, 0.f },
    { 3.f/40.f, 9.f/40.f, 0.f, 0.f, 0.f },
    { 44.f/45.f, -56.f/15.f, 32.f/9.f, 0.f, 0.f },
    { 19372.f/6561.f, -25360.f/2187.f, 64448.f/6561.f, -212.f/729.f, 0.f },
    { 9017.f/3168.f, -355.f/33.f, 46732.f/5247.f, 49.f/176.f, -5103.f/18656.f },
};
__constant__ float DP_C[6] = { 0.f, 1.f/5.f, 3.f/10.f, 4.f/5.f, 8.f/9.f, 1.f };

// N=256 layer. 4 warps: rowgroup rg=w&1 (rows 8*rg..+7), colgroup g=w>>1
// (cols 128*g + 4*lane..+3). acc[q][c] = (out[r0+2q], out[r0+2q+1]) for col c.
// Activation pairs are natural from ulonglong2 LDS; weights dup2'd (4 movs/k).
template<int K, bool TANH>
__device__ __forceinline__ void dense256(
    const float* __restrict__ W, const float* __restrict__ bias,
    const float* __restrict__ sA, float* __restrict__ sOut,
    int lane, int g, int r0)
{
    u64 acc[4][4];
    {
        float4 b = *(const float4*)(bias + 128*g + 4*lane);
        u64 b0 = dup2(b.x), b1 = dup2(b.y), b2 = dup2(b.z), b3 = dup2(b.w);
#pragma unroll
        for (int q = 0; q < 4; q++) {
            acc[q][0] = b0; acc[q][1] = b1; acc[q][2] = b2; acc[q][3] = b3;
        }
    }

    const float* w0 = W + 128*g + 4*lane;
    const float* aP = sA + r0;

    float4 wb[RD];                     // depth-8 weight ring (raw float4)
#pragma unroll
    for (int s = 0; s < RD; s++) wb[s] = ldg4(w0 + s*Hh);

    u64 ab[2][4];                      // natural (r,r+1) act pairs, 8 rows
    {
        ulonglong2 t0 = *(const ulonglong2*)(aP);
        ulonglong2 t1 = *(const ulonglong2*)(aP + 4);
        ab[0][0] = t0.x; ab[0][1] = t0.y; ab[0][2] = t1.x; ab[0][3] = t1.y;
    }

    int k = 0;
#pragma unroll 8
    for (; k < K - RD; k++) {
        const int slot = k & (RD-1), pb = k & 1;
        float4 wf = wb[slot];
        wb[slot] = ldg4(w0 + (k + RD)*Hh);
        {
            const float* ap1 = aP + (k+1)*STRA;
            ulonglong2 t0 = *(const ulonglong2*)(ap1);
            ulonglong2 t1 = *(const ulonglong2*)(ap1 + 4);
            ab[pb^1][0] = t0.x; ab[pb^1][1] = t0.y;
            ab[pb^1][2] = t1.x; ab[pb^1][3] = t1.y;
        }
        u64 wA = dup2(wf.x), wB = dup2(wf.y), wC = dup2(wf.z), wD = dup2(wf.w);
#pragma unroll
        for (int q = 0; q < 4; q++) {
            u64 a = ab[pb][q];
            fma2(acc[q][0], a, wA);
            fma2(acc[q][1], a, wB);
            fma2(acc[q][2], a, wC);
            fma2(acc[q][3], a, wD);
        }
    }
#pragma unroll
    for (; k < K; k++) {               // tail: ring holds k..K-1
        const int slot = k & (RD-1), pb = k & 1;
        float4 wf = wb[slot];
        if (k + 1 < K) {
            const float* ap1 = aP + (k+1)*STRA;
            ulonglong2 t0 = *(const ulonglong2*)(ap1);
            ulonglong2 t1 = *(const ulonglong2*)(ap1 + 4);
            ab[pb^1][0] = t0.x; ab[pb^1][1] = t0.y;
            ab[pb^1][2] = t1.x; ab[pb^1][3] = t1.y;
        }
        u64 wA = dup2(wf.x), wB = dup2(wf.y), wC = dup2(wf.z), wD = dup2(wf.w);
#pragma unroll
        for (int q = 0; q < 4; q++) {
            u64 a = ab[pb][q];
            fma2(acc[q][0], a, wA);
            fma2(acc[q][1], a, wB);
            fma2(acc[q][2], a, wC);
            fma2(acc[q][3], a, wD);
        }
    }

    const int rot = (lane >> 1) & 3;   // stagger stores across cols
#pragma unroll
    for (int cc = 0; cc < 4; cc++) {
        int c = (cc + rot) & 3;
        float v[8];
#pragma unroll
        for (int q = 0; q < 4; q++) {
            v[2*q]   = lo32(acc[q][c]);
            v[2*q+1] = hi32(acc[q][c]);
        }
        if (TANH) {
#pragma unroll
            for (int r = 0; r < 8; r++) v[r] = fast_tanh(v[r]);
        }
        float* o = sOut + (128*g + 4*lane + c)*STRA + r0;
        *(float4*)(o)     = make_float4(v[0], v[1], v[2], v[3]);
        *(float4*)(o + 4) = make_float4(v[4], v[5], v[6], v[7]);
    }
}

// N=64 output layer (K=256). 4 warps: warp w -> rows 4w..4w+3;
// thread: cols (2*lane, 2*lane+1) x 4 rows. Row-pair accs; natural act pairs.
__device__ __forceinline__ void dense64out(
    const float* __restrict__ W, const float* __restrict__ bias,
    const float* __restrict__ sA, float* __restrict__ sKs,
    int lane, int r0d)
{
    u64 acc[2][2];   // [row-pair][col]
    {
        float2 bb = *(const float2*)(bias + 2*lane);
        u64 b0 = dup2(bb.x), b1 = dup2(bb.y);
        acc[0][0] = b0; acc[1][0] = b0;
        acc[0][1] = b1; acc[1][1] = b1;
    }
    const float* w0 = W + 2*lane;
    const float* aP = sA + r0d;

    float2 wb[RD];
#pragma unroll
    for (int s = 0; s < RD; s++) wb[s] = ldg2f(w0 + s*Dd);
    u64 ab[2][2];
    {
        ulonglong2 t = *(const ulonglong2*)(aP);
        ab[0][0] = t.x; ab[0][1] = t.y;
    }

    int k = 0;
#pragma unroll 8
    for (; k < Hh - RD; k++) {
        const int slot = k & (RD-1), pb = k & 1;
        float2 wf = wb[slot];
        wb[slot] = ldg2f(w0 + (k + RD)*Dd);
        {
            ulonglong2 t = *(const ulonglong2*)(aP + (k+1)*STRA);
            ab[pb^1][0] = t.x; ab[pb^1][1] = t.y;
        }
        u64 wA = dup2(wf.x), wB = dup2(wf.y);
        fma2(acc[0][0], ab[pb][0], wA); fma2(acc[1][0], ab[pb][1], wA);
        fma2(acc[0][1], ab[pb][0], wB); fma2(acc[1][1], ab[pb][1], wB);
    }
#pragma unroll
    for (; k < Hh; k++) {
        const int slot = k & (RD-1), pb = k & 1;
        float2 wf = wb[slot];
        if (k + 1 < Hh) {
            ulonglong2 t = *(const ulonglong2*)(aP + (k+1)*STRA);
            ab[pb^1][0] = t.x; ab[pb^1][1] = t.y;
        }
        u64 wA = dup2(wf.x), wB = dup2(wf.y);
        fma2(acc[0][0], ab[pb][0], wA); fma2(acc[1][0], ab[pb][1], wA);
        fma2(acc[0][1], ab[pb][0], wB); fma2(acc[1][1], ab[pb][1], wB);
    }

    float* p0 = sKs + (2*lane    )*STRA + r0d;
    float* p1 = sKs + (2*lane + 1)*STRA + r0d;
    float4 v0 = make_float4(lo32(acc[0][0]), hi32(acc[0][0]),
                            lo32(acc[1][0]), hi32(acc[1][0]));
    float4 v1 = make_float4(lo32(acc[0][1]), hi32(acc[0][1]),
                            lo32(acc[1][1]), hi32(acc[1][1]));
    if ((lane >> 1) & 1) {
        *(float4*)p1 = v1; *(float4*)p0 = v0;
    } else {
        *(float4*)p0 = v0; *(float4*)p1 = v1;
    }
}

__global__ void __launch_bounds__(NT, 2)
ffjord_kernel(const float* __restrict__ x, float* __restrict__ out, FfjordParams P)
{
    extern __shared__ float sm[];
    float* sZ   = sm;                          // (Dd+1) x STRA
    float* sH1  = sZ + (Dd + 1) * STRA;        // Hh x STRA
    float* sH2  = sH1 + Hh * STRA;             // Hh x STRA
    float* sY   = sH2 + Hh * STRA;             // Dd x STRY
    float* sK   = sY + Dd * STRY;              // [6][Dd][STRA]

    const int tid   = threadIdx.x;
    const int lane  = tid & 31;
    const int w     = tid >> 5;                // 0..3
    const int r0    = (w & 1) * 8;             // dense256 rowgroup (8 rows)
    const int g     = w >> 1;                  // dense256 colgroup
    const int r0d   = w * 4;                   // dense64 rowgroup (4 rows)
    const int rbase = blockIdx.x * MROWS;

    for (int i = tid; i < MROWS * Dd; i += NT) {
        int r = i >> 6, d = i & 63;
        sY[d * STRY + r] = x[(rbase + r) * Dd + d];
    }
    __syncthreads();

    const float h = 1.0f / 16.0f;

    for (int bij = 0; bij < 2; bij++) {
        const float* W1 = P.W1[bij]; const float* b1 = P.b1[bij];
        const float* W2 = P.W2[bij]; const float* b2 = P.b2[bij];
        const float* W3 = P.W3[bij]; const float* b3 = P.b3[bij];

        for (int step = 0; step < NSTEPS; step++) {
            float t0 = (float)step * h;

            for (int s = 0; s < 6; s++) {
                float tstage = t0 + DP_C[s] * h;
                float ha[5];
#pragma unroll
                for (int l = 0; l < 5; l++) ha[l] = h * DP_A[s][l];

                for (int i = tid; i < (Dd + 1) * MROWS; i += NT) {
                    int d = i >> 4, r = i & 15;
                    float z;
                    if (d == Dd) {
                        z = tstage;
                    } else {
                        z = sY[d * STRY + r];
#pragma unroll
                        for (int l = 0; l < 5; l++)
                            if (l < s) z += ha[l] * sK[(l * Dd + d) * STRA + r];
                    }
                    sZ[d * STRA + r] = z;
                }
                __syncthreads();

                dense256<Dd + 1, true>(W1, b1, sZ,  sH1, lane, g, r0);
                __syncthreads();
                dense256<Hh,     true>(W2, b2, sH1, sH2, lane, g, r0);
                __syncthreads();
                dense64out(W3, b3, sH2, sK + s * Dd * STRA, lane, r0d);
                __syncthreads();
            }

            for (int i = tid; i < Dd * MROWS; i += NT) {
                int d = i >> 4, r = i & 15;
                int ok = d * STRA + r;
                float acc = (35.f/384.f)     * sK[ok]
                          + (500.f/1113.f)   * sK[(2*Dd)*STRA + ok]
                          + (125.f/192.f)    * sK[(3*Dd)*STRA + ok]
                          + (-2187.f/6784.f) * sK[(4*Dd)*STRA + ok]
                          + (11.f/84.f)      * sK[(5*Dd)*STRA + ok];
                sY[d * STRY + r] += h * acc;
            }
            __syncthreads();
        }
    }

    for (int i = tid; i < MROWS * Dd; i += NT) {
        int r = i >> 6, d = i & 63;
        out[(rbase + r) * Dd + d] = sY[d * STRY + r];
    }
}

extern "C" void kernel_launch(void* const* d_in, const int* in_sizes, int n_in,
                              void* d_out, int out_size)
{
    (void)in_sizes; (void)n_in; (void)out_size;
    const float* x = (const float*)d_in[0];

    FfjordParams P;
    P.W1[0] = (const float*)d_in[1];  P.b1[0] = (const float*)d_in[2];
    P.W2[0] = (const float*)d_in[3];  P.b2[0] = (const float*)d_in[4];
    P.W3[0] = (const float*)d_in[5];  P.b3[0] = (const float*)d_in[6];
    P.W1[1] = (const float*)d_in[7];  P.b1[1] = (const float*)d_in[8];
    P.W2[1] = (const float*)d_in[9];  P.b2[1] = (const float*)d_in[10];
    P.W3[1] = (const float*)d_in[11]; P.b3[1] = (const float*)d_in[12];

    static_assert(SM_BYTES <= 100 * 1024, "smem budget (2 CTAs/SM)");
    cudaFuncSetAttribute(ffjord_kernel, cudaFuncAttributeMaxDynamicSharedMemorySize, SM_BYTES);

    ffjord_kernel<<<NCTAS, NT, SM_BYTES>>>(x, (float*)d_out, P);
}

// round 12
// speedup vs baseline: 2.2883x; 1.0791x over previous
#include <cuda_runtime.h>

// FFJORD: 2 chained fixed-step DOPRI5 integrations of a (64+1)->256->256->64 MLP.
// One CTA integrates 16 batch rows. fp32 via fma.rn.f32x2.
// R12 = R11 + fused glue: dense64's epilogue computes the next stage input Z
// (and on s=5 the full RK y-update) directly from its in-register k values.
// Removes Z-build + RK phases and 7 syncs/step (25 -> 18); k6 never hits smem.

typedef unsigned long long u64;

#define Dd     64
#define Hh     256
#define MROWS  16
#define STRA   20      // plain activation stride (floats, 80B rows)
#define STRY   16
#define NT     128
#define NSTEPS 16
#define NCTAS  (4096 / MROWS)   // 256
#define RD     8       // weight prefetch ring depth

// smem: sZ[(Dd+1)][STRA] + sH1[Hh][STRA] + sH2[Hh][STRA] + sY[Dd][STRY] + sK[6][Dd][STRA]
#define SM_FLOATS ((Dd + 1 + Hh + Hh + 6*Dd) * STRA + Dd * STRY)
#define SM_BYTES  (SM_FLOATS * 4)    // 80,976 B -> 2 CTAs/SM

struct FfjordParams {
    const float* W1[2]; const float* b1[2];
    const float* W2[2]; const float* b2[2];
    const float* W3[2]; const float* b3[2];
};

__device__ __forceinline__ u64 dup2(float v) {
    u64 r; asm("mov.b64 %0, {%1, %1};" : "=l"(r) : "r"(__float_as_uint(v)));
    return r;
}
__device__ __forceinline__ void fma2(u64& d, u64 a, u64 b) {
    asm("fma.rn.f32x2 %0, %1, %2, %3;" : "=l"(d) : "l"(a), "l"(b), "l"(d));
}
__device__ __forceinline__ float lo32(u64 v){ return __uint_as_float((unsigned)v); }
__device__ __forceinline__ float hi32(u64 v){ return __uint_as_float((unsigned)(v>>32)); }

__device__ __forceinline__ float4 ldg4(const float* p) {
    float4 v;
    asm("ld.global.nc.v4.f32 {%0,%1,%2,%3}, [%4];"
        : "=f"(v.x), "=f"(v.y), "=f"(v.z), "=f"(v.w) : "l"(p));
    return v;
}
__device__ __forceinline__ float2 ldg2f(const float* p) {
    float2 v;
    asm("ld.global.nc.v2.f32 {%0,%1}, [%2];" : "=f"(v.x), "=f"(v.y) : "l"(p));
    return v;
}

__device__ __forceinline__ float fast_tanh(float x) {
    float u = __expf(2.0f * x);
    return 1.0f - __fdividef(2.0f, u + 1.0f);
}

__device__ __forceinline__ float4 f4_fma(float c, float4 a, float4 acc) {
    return make_float4(fmaf(c, a.x, acc.x), fmaf(c, a.y, acc.y),
                       fmaf(c, a.z, acc.z), fmaf(c, a.w, acc.w));
}

__constant__ float DP_A[6][5] = {
    { 0.f, 0.f, 0.f, 0.f, 0.f },
    { 1.f/5.f, 0.f, 0.f, 0.f, 0.f },
    { 3.f/40.f, 9.f/40.f, 0.f, 0.f, 0.f },
    { 44.f/45.f, -56.f/15.f, 32.f/9.f, 0.f, 0.f },
    { 19372.f/6561.f, -25360.f/2187.f, 64448.f/6561.f, -212.f/729.f, 0.f },
    { 9017.f/3168.f, -355.f/33.f, 46732.f/5247.f, 49.f/176.f, -5103.f/18656.f },
};
__constant__ float DP_C[6] = { 0.f, 1.f/5.f, 3.f/10.f, 4.f/5.f, 8.f/9.f, 1.f };
__constant__ float DP_B[6] = { 35.f/384.f, 0.f, 500.f/1113.f, 125.f/192.f,
                               -2187.f/6784.f, 11.f/84.f };

// N=256 layer (unchanged from R11). 4 warps: rowgroup rg=w&1 (rows 8*rg..+7),
// colgroup g=w>>1 (cols 128*g + 4*lane..+3). Row-pair accumulators.
template<int K, bool TANH>
__device__ __forceinline__ void dense256(
    const float* __restrict__ W, const float* __restrict__ bias,
    const float* __restrict__ sA, float* __restrict__ sOut,
    int lane, int g, int r0)
{
    u64 acc[4][4];
    {
        float4 b = *(const float4*)(bias + 128*g + 4*lane);
        u64 b0 = dup2(b.x), b1 = dup2(b.y), b2 = dup2(b.z), b3 = dup2(b.w);
#pragma unroll
        for (int q = 0; q < 4; q++) {
            acc[q][0] = b0; acc[q][1] = b1; acc[q][2] = b2; acc[q][3] = b3;
        }
    }

    const float* w0 = W + 128*g + 4*lane;
    const float* aP = sA + r0;

    float4 wb[RD];
#pragma unroll
    for (int s = 0; s < RD; s++) wb[s] = ldg4(w0 + s*Hh);

    u64 ab[2][4];
    {
        ulonglong2 t0 = *(const ulonglong2*)(aP);
        ulonglong2 t1 = *(const ulonglong2*)(aP + 4);
        ab[0][0] = t0.x; ab[0][1] = t0.y; ab[0][2] = t1.x; ab[0][3] = t1.y;
    }

    int k = 0;
#pragma unroll 8
    for (; k < K - RD; k++) {
        const int slot = k & (RD-1), pb = k & 1;
        float4 wf = wb[slot];
        wb[slot] = ldg4(w0 + (k + RD)*Hh);
        {
            const float* ap1 = aP + (k+1)*STRA;
            ulonglong2 t0 = *(const ulonglong2*)(ap1);
            ulonglong2 t1 = *(const ulonglong2*)(ap1 + 4);
            ab[pb^1][0] = t0.x; ab[pb^1][1] = t0.y;
            ab[pb^1][2] = t1.x; ab[pb^1][3] = t1.y;
        }
        u64 wA = dup2(wf.x), wB = dup2(wf.y), wC = dup2(wf.z), wD = dup2(wf.w);
#pragma unroll
        for (int q = 0; q < 4; q++) {
            u64 a = ab[pb][q];
            fma2(acc[q][0], a, wA);
            fma2(acc[q][1], a, wB);
            fma2(acc[q][2], a, wC);
            fma2(acc[q][3], a, wD);
        }
    }
#pragma unroll
    for (; k < K; k++) {
        const int slot = k & (RD-1), pb = k & 1;
        float4 wf = wb[slot];
        if (k + 1 < K) {
            const float* ap1 = aP + (k+1)*STRA;
            ulonglong2 t0 = *(const ulonglong2*)(ap1);
            ulonglong2 t1 = *(const ulonglong2*)(ap1 + 4);
            ab[pb^1][0] = t0.x; ab[pb^1][1] = t0.y;
            ab[pb^1][2] = t1.x; ab[pb^1][3] = t1.y;
        }
        u64 wA = dup2(wf.x), wB = dup2(wf.y), wC = dup2(wf.z), wD = dup2(wf.w);
#pragma unroll
        for (int q = 0; q < 4; q++) {
            u64 a = ab[pb][q];
            fma2(acc[q][0], a, wA);
            fma2(acc[q][1], a, wB);
            fma2(acc[q][2], a, wC);
            fma2(acc[q][3], a, wD);
        }
    }

    const int rot = (lane >> 1) & 3;
#pragma unroll
    for (int cc = 0; cc < 4; cc++) {
        int c = (cc + rot) & 3;
        float v[8];
#pragma unroll
        for (int q = 0; q < 4; q++) {
            v[2*q]   = lo32(acc[q][c]);
            v[2*q+1] = hi32(acc[q][c]);
        }
        if (TANH) {
#pragma unroll
            for (int r = 0; r < 8; r++) v[r] = fast_tanh(v[r]);
        }
        float* o = sOut + (128*g + 4*lane + c)*STRA + r0;
        *(float4*)(o)     = make_float4(v[0], v[1], v[2], v[3]);
        *(float4*)(o + 4) = make_float4(v[4], v[5], v[6], v[7]);
    }
}

// N=64 output layer with FUSED stage glue. Thread owns features c0=2*lane,
// c1=2*lane+1 x rows r0d..r0d+3. After the GEMM it:
//   - stores k_s to sK (if s<5; k6 never needs smem),
//   - computes z = y + sum_{l<s} cf[l]*k_l + cfr*k_s  and writes sZ,
//   - on s==5 (cf = RK b-coeffs) also writes y_new to sY,
//   - lane0 writes the time row sZ[64][*] = tnext.
__device__ __forceinline__ void dense64_fused(
    const float* __restrict__ W, const float* __restrict__ bias,
    const float* __restrict__ sA, float* __restrict__ sK,
    float* __restrict__ sY, float* __restrict__ sZ,
    const float cf[5], float cfr, int s, float tnext, bool writeY,
    int lane, int r0d)
{
    u64 acc[2][2];   // [row-pair][col]
    {
        float2 bb = *(const float2*)(bias + 2*lane);
        u64 b0 = dup2(bb.x), b1 = dup2(bb.y);
        acc[0][0] = b0; acc[1][0] = b0;
        acc[0][1] = b1; acc[1][1] = b1;
    }
    const float* w0 = W + 2*lane;
    const float* aP = sA + r0d;

    float2 wb[RD];
#pragma unroll
    for (int q = 0; q < RD; q++) wb[q] = ldg2f(w0 + q*Dd);
    u64 ab[2][2];
    {
        ulonglong2 t = *(const ulonglong2*)(aP);
        ab[0][0] = t.x; ab[0][1] = t.y;
    }

    int k = 0;
#pragma unroll 8
    for (; k < Hh - RD; k++) {
        const int slot = k & (RD-1), pb = k & 1;
        float2 wf = wb[slot];
        wb[slot] = ldg2f(w0 + (k + RD)*Dd);
        {
            ulonglong2 t = *(const ulonglong2*)(aP + (k+1)*STRA);
            ab[pb^1][0] = t.x; ab[pb^1][1] = t.y;
        }
        u64 wA = dup2(wf.x), wB = dup2(wf.y);
        fma2(acc[0][0], ab[pb][0], wA); fma2(acc[1][0], ab[pb][1], wA);
        fma2(acc[0][1], ab[pb][0], wB); fma2(acc[1][1], ab[pb][1], wB);
    }
#pragma unroll
    for (; k < Hh; k++) {
        const int slot = k & (RD-1), pb = k & 1;
        float2 wf = wb[slot];
        if (k + 1 < Hh) {
            ulonglong2 t = *(const ulonglong2*)(aP + (k+1)*STRA);
            ab[pb^1][0] = t.x; ab[pb^1][1] = t.y;
        }
        u64 wA = dup2(wf.x), wB = dup2(wf.y);
        fma2(acc[0][0], ab[pb][0], wA); fma2(acc[1][0], ab[pb][1], wA);
        fma2(acc[0][1], ab[pb][0], wB); fma2(acc[1][1], ab[pb][1], wB);
    }

    const int c0 = 2*lane, c1 = 2*lane + 1;
    float4 v0 = make_float4(lo32(acc[0][0]), hi32(acc[0][0]),
                            lo32(acc[1][0]), hi32(acc[1][0]));  // k_s[c0][r0d..+3]
    float4 v1 = make_float4(lo32(acc[0][1]), hi32(acc[0][1]),
                            lo32(acc[1][1]), hi32(acc[1][1]));  // k_s[c1][r0d..+3]

    if (s < 5) {   // k6 only feeds the fused y-update; never stored
        float* kd = sK + s * Dd * STRA;
        float* p0 = kd + c0*STRA + r0d;
        float* p1 = kd + c1*STRA + r0d;
        if ((lane >> 1) & 1) { *(float4*)p1 = v1; *(float4*)p0 = v0; }
        else                 { *(float4*)p0 = v0; *(float4*)p1 = v1; }
    }

    // z = y + sum_{l<s} cf[l]*k_l + cfr*k_s
    float4 z0 = *(const float4*)(sY + c0*STRY + r0d);
    float4 z1 = *(const float4*)(sY + c1*STRY + r0d);
    z0 = f4_fma(cfr, v0, z0);
    z1 = f4_fma(cfr, v1, z1);
#pragma unroll
    for (int l = 0; l < 5; l++) {
        if (l < s) {
            const float* kb = sK + l * Dd * STRA;
            float4 k0 = *(const float4*)(kb + c0*STRA + r0d);
            float4 k1 = *(const float4*)(kb + c1*STRA + r0d);
            z0 = f4_fma(cf[l], k0, z0);
            z1 = f4_fma(cf[l], k1, z1);
        }
    }
    *(float4*)(sZ + c0*STRA + r0d) = z0;
    *(float4*)(sZ + c1*STRA + r0d) = z1;
    if (writeY) {
        *(float4*)(sY + c0*STRY + r0d) = z0;
        *(float4*)(sY + c1*STRY + r0d) = z1;
    }
    if (lane == 0)
        *(float4*)(sZ + Dd*STRA + r0d) = make_float4(tnext, tnext, tnext, tnext);
}

__global__ void __launch_bounds__(NT, 2)
ffjord_kernel(const float* __restrict__ x, float* __restrict__ out, FfjordParams P)
{
    extern __shared__ float sm[];
    float* sZ   = sm;                          // (Dd+1) x STRA
    float* sH1  = sZ + (Dd + 1) * STRA;        // Hh x STRA
    float* sH2  = sH1 + Hh * STRA;             // Hh x STRA
    float* sY   = sH2 + Hh * STRA;             // Dd x STRY
    float* sK   = sY + Dd * STRY;              // [6][Dd][STRA] (slot 5 unused)

    const int tid   = threadIdx.x;
    const int lane  = tid & 31;
    const int w     = tid >> 5;                // 0..3
    const int r0    = (w & 1) * 8;             // dense256 rowgroup (8 rows)
    const int g     = w >> 1;                  // dense256 colgroup
    const int r0d   = w * 4;                   // dense64 rowgroup (4 rows)
    const int rbase = blockIdx.x * MROWS;

    // Load x into sY and sZ (initial stage input; t-row = 0).
    for (int i = tid; i < MROWS * Dd; i += NT) {
        int r = i >> 6, d = i & 63;
        float v = x[(rbase + r) * Dd + d];
        sY[d * STRY + r] = v;
        sZ[d * STRA + r] = v;
    }
    for (int i = tid; i < MROWS; i += NT) sZ[Dd * STRA + i] = 0.0f;
    __syncthreads();

    const float h = 1.0f / 16.0f;

    for (int bij = 0; bij < 2; bij++) {
        const float* W1 = P.W1[bij]; const float* b1 = P.b1[bij];
        const float* W2 = P.W2[bij]; const float* b2 = P.b2[bij];
        const float* W3 = P.W3[bij]; const float* b3 = P.b3[bij];

        for (int step = 0; step < NSTEPS; step++) {
            float t0 = (float)step * h;

            for (int s = 0; s < 6; s++) {
                dense256<Dd + 1, true>(W1, b1, sZ,  sH1, lane, g, r0);
                __syncthreads();
                dense256<Hh,     true>(W2, b2, sH1, sH2, lane, g, r0);
                __syncthreads();

                float cf[5], cfr, tnext;
                bool writeY = (s == 5);
                if (s < 5) {
#pragma unroll
                    for (int l = 0; l < 5; l++) cf[l] = h * DP_A[s+1][l];
                    cfr = h * DP_A[s+1][s];
                    tnext = t0 + DP_C[s+1] * h;
                } else {
#pragma unroll
                    for (int l = 0; l < 5; l++) cf[l] = h * DP_B[l];
                    cfr = h * DP_B[5];
                    tnext = (step == NSTEPS - 1) ? 0.0f : (float)(step + 1) * h;
                }
                dense64_fused(W3, b3, sH2, sK, sY, sZ,
                              cf, cfr, s, tnext, writeY, lane, r0d);
                __syncthreads();
            }
        }
    }

    for (int i = tid; i < MROWS * Dd; i += NT) {
        int r = i >> 6, d = i & 63;
        out[(rbase + r) * Dd + d] = sY[d * STRY + r];
    }
}

extern "C" void kernel_launch(void* const* d_in, const int* in_sizes, int n_in,
                              void* d_out, int out_size)
{
    (void)in_sizes; (void)n_in; (void)out_size;
    const float* x = (const float*)d_in[0];

    FfjordParams P;
    P.W1[0] = (const float*)d_in[1];  P.b1[0] = (const float*)d_in[2];
    P.W2[0] = (const float*)d_in[3];  P.b2[0] = (const float*)d_in[4];
    P.W3[0] = (const float*)d_in[5];  P.b3[0] = (const float*)d_in[6];
    P.W1[1] = (const float*)d_in[7];  P.b1[1] = (const float*)d_in[8];
    P.W2[1] = (const float*)d_in[9];  P.b2[1] = (const float*)d_in[10];
    P.W3[1] = (const float*)d_in[11]; P.b3[1] = (const float*)d_in[12];

    static_assert(SM_BYTES <= 100 * 1024, "smem budget (2 CTAs/SM)");
    cudaFuncSetAttribute(ffjord_kernel, cudaFuncAttributeMaxDynamicSharedMemorySize, SM_BYTES);

    ffjord_kernel<<<NCTAS, NT, SM_BYTES>>>(x, (float*)d_out, P);
}

// round 13
// speedup vs baseline: 2.3248x; 1.0160x over previous
#include <cuda_runtime.h>

// FFJORD: 2 chained fixed-step DOPRI5 integrations of a (64+1)->256->256->64 MLP.
// One CTA integrates 16 batch rows. fp32 via fma.rn.f32x2.
// R13 = R12 + tanh.approx.f32 (1 MUFU vs 2, halves the epilogue MUFU bubble)
//           + distance-2 activation prefetch (LDS 29-cyc latency fully covered,
//             zero extra registers: consume ab[k&1], reload same slot with k+2).

typedef unsigned long long u64;

#define Dd     64
#define Hh     256
#define MROWS  16
#define STRA   20      // plain activation stride (floats, 80B rows)
#define STRY   16
#define NT     128
#define NSTEPS 16
#define NCTAS  (4096 / MROWS)   // 256
#define RD     8       // weight prefetch ring depth

// smem: sZ[(Dd+1)][STRA] + sH1[Hh][STRA] + sH2[Hh][STRA] + sY[Dd][STRY] + sK[6][Dd][STRA]
#define SM_FLOATS ((Dd + 1 + Hh + Hh + 6*Dd) * STRA + Dd * STRY)
#define SM_BYTES  (SM_FLOATS * 4)    // 80,976 B -> 2 CTAs/SM

struct FfjordParams {
    const float* W1[2]; const float* b1[2];
    const float* W2[2]; const float* b2[2];
    const float* W3[2]; const float* b3[2];
};

__device__ __forceinline__ u64 dup2(float v) {
    u64 r; asm("mov.b64 %0, {%1, %1};" : "=l"(r) : "r"(__float_as_uint(v)));
    return r;
}
__device__ __forceinline__ void fma2(u64& d, u64 a, u64 b) {
    asm("fma.rn.f32x2 %0, %1, %2, %3;" : "=l"(d) : "l"(a), "l"(b), "l"(d));
}
__device__ __forceinline__ float lo32(u64 v){ return __uint_as_float((unsigned)v); }
__device__ __forceinline__ float hi32(u64 v){ return __uint_as_float((unsigned)(v>>32)); }

__device__ __forceinline__ float4 ldg4(const float* p) {
    float4 v;
    asm("ld.global.nc.v4.f32 {%0,%1,%2,%3}, [%4];"
        : "=f"(v.x), "=f"(v.y), "=f"(v.z), "=f"(v.w) : "l"(p));
    return v;
}
__device__ __forceinline__ float2 ldg2f(const float* p) {
    float2 v;
    asm("ld.global.nc.v2.f32 {%0,%1}, [%2];" : "=f"(v.x), "=f"(v.y) : "l"(p));
    return v;
}

// single-MUFU tanh (sm_75+): max rel err ~5e-4, fine for 1e-3 tolerance
__device__ __forceinline__ float fast_tanh(float x) {
    float r; asm("tanh.approx.f32 %0, %1;" : "=f"(r) : "f"(x)); return r;
}

__device__ __forceinline__ float4 f4_fma(float c, float4 a, float4 acc) {
    return make_float4(fmaf(c, a.x, acc.x), fmaf(c, a.y, acc.y),
                       fmaf(c, a.z, acc.z), fmaf(c, a.w, acc.w));
}

__constant__ float DP_A[6][5] = {
    { 0.f, 0.f, 0.f, 0.f, 0.f },
    { 1.f/5.f, 0.f, 0.f, 0.f, 0.f },
    { 3.f/40.f, 9.f/40.f, 0.f, 0.f, 0.f },
    { 44.f/45.f, -56.f/15.f, 32.f/9.f, 0.f, 0.f },
    { 19372.f/6561.f, -25360.f/2187.f, 64448.f/6561.f, -212.f/729.f, 0.f },
    { 9017.f/3168.f, -355.f/33.f, 46732.f/5247.f, 49.f/176.f, -5103.f/18656.f },
};
__constant__ float DP_C[6] = { 0.f, 1.f/5.f, 3.f/10.f, 4.f/5.f, 8.f/9.f, 1.f };
__constant__ float DP_B[6] = { 35.f/384.f, 0.f, 500.f/1113.f, 125.f/192.f,
                               -2187.f/6784.f, 11.f/84.f };

// N=256 layer. 4 warps: rowgroup rg=w&1 (rows 8*rg..+7), colgroup g=w>>1
// (cols 128*g + 4*lane..+3). Row-pair accumulators; dist-2 act prefetch.
template<int K, bool TANH>
__device__ __forceinline__ void dense256(
    const float* __restrict__ W, const float* __restrict__ bias,
    const float* __restrict__ sA, float* __restrict__ sOut,
    int lane, int g, int r0)
{
    u64 acc[4][4];
    {
        float4 b = *(const float4*)(bias + 128*g + 4*lane);
        u64 b0 = dup2(b.x), b1 = dup2(b.y), b2 = dup2(b.z), b3 = dup2(b.w);
#pragma unroll
        for (int q = 0; q < 4; q++) {
            acc[q][0] = b0; acc[q][1] = b1; acc[q][2] = b2; acc[q][3] = b3;
        }
    }

    const float* w0 = W + 128*g + 4*lane;
    const float* aP = sA + r0;

    float4 wb[RD];
#pragma unroll
    for (int s = 0; s < RD; s++) wb[s] = ldg4(w0 + s*Hh);

    u64 ab[2][4];                      // dist-2 act prefetch (k and k+1 in flight)
#pragma unroll
    for (int s = 0; s < 2; s++) {
        ulonglong2 t0 = *(const ulonglong2*)(aP + s*STRA);
        ulonglong2 t1 = *(const ulonglong2*)(aP + s*STRA + 4);
        ab[s][0] = t0.x; ab[s][1] = t0.y; ab[s][2] = t1.x; ab[s][3] = t1.y;
    }

    int k = 0;
#pragma unroll 8
    for (; k < K - RD; k++) {          // RD >= 2 so k+2 < K here
        const int slot = k & (RD-1), pb = k & 1;
        float4 wf = wb[slot];
        wb[slot] = ldg4(w0 + (k + RD)*Hh);
        u64 a0 = ab[pb][0], a1 = ab[pb][1], a2 = ab[pb][2], a3 = ab[pb][3];
        {   // reload SAME slot with k+2
            const float* ap2 = aP + (k+2)*STRA;
            ulonglong2 t0 = *(const ulonglong2*)(ap2);
            ulonglong2 t1 = *(const ulonglong2*)(ap2 + 4);
            ab[pb][0] = t0.x; ab[pb][1] = t0.y;
            ab[pb][2] = t1.x; ab[pb][3] = t1.y;
        }
        u64 wA = dup2(wf.x), wB = dup2(wf.y), wC = dup2(wf.z), wD = dup2(wf.w);
        fma2(acc[0][0], a0, wA); fma2(acc[0][1], a0, wB);
        fma2(acc[0][2], a0, wC); fma2(acc[0][3], a0, wD);
        fma2(acc[1][0], a1, wA); fma2(acc[1][1], a1, wB);
        fma2(acc[1][2], a1, wC); fma2(acc[1][3], a1, wD);
        fma2(acc[2][0], a2, wA); fma2(acc[2][1], a2, wB);
        fma2(acc[2][2], a2, wC); fma2(acc[2][3], a2, wD);
        fma2(acc[3][0], a3, wA); fma2(acc[3][1], a3, wB);
        fma2(acc[3][2], a3, wC); fma2(acc[3][3], a3, wD);
    }
#pragma unroll
    for (; k < K; k++) {               // tail: weight ring holds k..K-1
        const int slot = k & (RD-1), pb = k & 1;
        float4 wf = wb[slot];
        u64 a0 = ab[pb][0], a1 = ab[pb][1], a2 = ab[pb][2], a3 = ab[pb][3];
        if (k + 2 < K) {
            const float* ap2 = aP + (k+2)*STRA;
            ulonglong2 t0 = *(const ulonglong2*)(ap2);
            ulonglong2 t1 = *(const ulonglong2*)(ap2 + 4);
            ab[pb][0] = t0.x; ab[pb][1] = t0.y;
            ab[pb][2] = t1.x; ab[pb][3] = t1.y;
        }
        u64 wA = dup2(wf.x), wB = dup2(wf.y), wC = dup2(wf.z), wD = dup2(wf.w);
        fma2(acc[0][0], a0, wA); fma2(acc[0][1], a0, wB);
        fma2(acc[0][2], a0, wC); fma2(acc[0][3], a0, wD);
        fma2(acc[1][0], a1, wA); fma2(acc[1][1], a1, wB);
        fma2(acc[1][2], a1, wC); fma2(acc[1][3], a1, wD);
        fma2(acc[2][0], a2, wA); fma2(acc[2][1], a2, wB);
        fma2(acc[2][2], a2, wC); fma2(acc[2][3], a2, wD);
        fma2(acc[3][0], a3, wA); fma2(acc[3][1], a3, wB);
        fma2(acc[3][2], a3, wC); fma2(acc[3][3], a3, wD);
    }

    const int rot = (lane >> 1) & 3;
#pragma unroll
    for (int cc = 0; cc < 4; cc++) {
        int c = (cc + rot) & 3;
        float v[8];
#pragma unroll
        for (int q = 0; q < 4; q++) {
            v[2*q]   = lo32(acc[q][c]);
            v[2*q+1] = hi32(acc[q][c]);
        }
        if (TANH) {
#pragma unroll
            for (int r = 0; r < 8; r++) v[r] = fast_tanh(v[r]);
        }
        float* o = sOut + (128*g + 4*lane + c)*STRA + r0;
        *(float4*)(o)     = make_float4(v[0], v[1], v[2], v[3]);
        *(float4*)(o + 4) = make_float4(v[4], v[5], v[6], v[7]);
    }
}

// N=64 output layer with FUSED stage glue (see R12). Dist-2 act prefetch.
__device__ __forceinline__ void dense64_fused(
    const float* __restrict__ W, const float* __restrict__ bias,
    const float* __restrict__ sA, float* __restrict__ sK,
    float* __restrict__ sY, float* __restrict__ sZ,
    const float cf[5], float cfr, int s, float tnext, bool writeY,
    int lane, int r0d)
{
    u64 acc[2][2];
    {
        float2 bb = *(const float2*)(bias + 2*lane);
        u64 b0 = dup2(bb.x), b1 = dup2(bb.y);
        acc[0][0] = b0; acc[1][0] = b0;
        acc[0][1] = b1; acc[1][1] = b1;
    }
    const float* w0 = W + 2*lane;
    const float* aP = sA + r0d;

    float2 wb[RD];
#pragma unroll
    for (int q = 0; q < RD; q++) wb[q] = ldg2f(w0 + q*Dd);
    u64 ab[2][2];
#pragma unroll
    for (int q = 0; q < 2; q++) {
        ulonglong2 t = *(const ulonglong2*)(aP + q*STRA);
        ab[q][0] = t.x; ab[q][1] = t.y;
    }

    int k = 0;
#pragma unroll 8
    for (; k < Hh - RD; k++) {
        const int slot = k & (RD-1), pb = k & 1;
        float2 wf = wb[slot];
        wb[slot] = ldg2f(w0 + (k + RD)*Dd);
        u64 a0 = ab[pb][0], a1 = ab[pb][1];
        {
            ulonglong2 t = *(const ulonglong2*)(aP + (k+2)*STRA);
            ab[pb][0] = t.x; ab[pb][1] = t.y;
        }
        u64 wA = dup2(wf.x), wB = dup2(wf.y);
        fma2(acc[0][0], a0, wA); fma2(acc[1][0], a1, wA);
        fma2(acc[0][1], a0, wB); fma2(acc[1][1], a1, wB);
    }
#pragma unroll
    for (; k < Hh; k++) {
        const int slot = k & (RD-1), pb = k & 1;
        float2 wf = wb[slot];
        u64 a0 = ab[pb][0], a1 = ab[pb][1];
        if (k + 2 < Hh) {
            ulonglong2 t = *(const ulonglong2*)(aP + (k+2)*STRA);
            ab[pb][0] = t.x; ab[pb][1] = t.y;
        }
        u64 wA = dup2(wf.x), wB = dup2(wf.y);
        fma2(acc[0][0], a0, wA); fma2(acc[1][0], a1, wA);
        fma2(acc[0][1], a0, wB); fma2(acc[1][1], a1, wB);
    }

    const int c0 = 2*lane, c1 = 2*lane + 1;
    float4 v0 = make_float4(lo32(acc[0][0]), hi32(acc[0][0]),
                            lo32(acc[1][0]), hi32(acc[1][0]));
    float4 v1 = make_float4(lo32(acc[0][1]), hi32(acc[0][1]),
                            lo32(acc[1][1]), hi32(acc[1][1]));

    if (s < 5) {
        float* kd = sK + s * Dd * STRA;
        float* p0 = kd + c0*STRA + r0d;
        float* p1 = kd + c1*STRA + r0d;
        if ((lane >> 1) & 1) { *(float4*)p1 = v1; *(float4*)p0 = v0; }
        else                 { *(float4*)p0 = v0; *(float4*)p1 = v1; }
    }

    float4 z0 = *(const float4*)(sY + c0*STRY + r0d);
    float4 z1 = *(const float4*)(sY + c1*STRY + r0d);
    z0 = f4_fma(cfr, v0, z0);
    z1 = f4_fma(cfr, v1, z1);
#pragma unroll
    for (int l = 0; l < 5; l++) {
        if (l < s) {
            const float* kb = sK + l * Dd * STRA;
            float4 k0 = *(const float4*)(kb + c0*STRA + r0d);
            float4 k1 = *(const float4*)(kb + c1*STRA + r0d);
            z0 = f4_fma(cf[l], k0, z0);
            z1 = f4_fma(cf[l], k1, z1);
        }
    }
    *(float4*)(sZ + c0*STRA + r0d) = z0;
    *(float4*)(sZ + c1*STRA + r0d) = z1;
    if (writeY) {
        *(float4*)(sY + c0*STRY + r0d) = z0;
        *(float4*)(sY + c1*STRY + r0d) = z1;
    }
    if (lane == 0)
        *(float4*)(sZ + Dd*STRA + r0d) = make_float4(tnext, tnext, tnext, tnext);
}

__global__ void __launch_bounds__(NT, 2)
ffjord_kernel(const float* __restrict__ x, float* __restrict__ out, FfjordParams P)
{
    extern __shared__ float sm[];
    float* sZ   = sm;                          // (Dd+1) x STRA
    float* sH1  = sZ + (Dd + 1) * STRA;        // Hh x STRA
    float* sH2  = sH1 + Hh * STRA;             // Hh x STRA
    float* sY   = sH2 + Hh * STRA;             // Dd x STRY
    float* sK   = sY + Dd * STRY;              // [6][Dd][STRA] (slot 5 unused)

    const int tid   = threadIdx.x;
    const int lane  = tid & 31;
    const int w     = tid >> 5;
    const int r0    = (w & 1) * 8;
    const int g     = w >> 1;
    const int r0d   = w * 4;
    const int rbase = blockIdx.x * MROWS;

    for (int i = tid; i < MROWS * Dd; i += NT) {
        int r = i >> 6, d = i & 63;
        float v = x[(rbase + r) * Dd + d];
        sY[d * STRY + r] = v;
        sZ[d * STRA + r] = v;
    }
    for (int i = tid; i < MROWS; i += NT) sZ[Dd * STRA + i] = 0.0f;
    __syncthreads();

    const float h = 1.0f / 16.0f;

    for (int bij = 0; bij < 2; bij++) {
        const float* W1 = P.W1[bij]; const float* b1 = P.b1[bij];
        const float* W2 = P.W2[bij]; const float* b2 = P.b2[bij];
        const float* W3 = P.W3[bij]; const float* b3 = P.b3[bij];

        for (int step = 0; step < NSTEPS; step++) {
            float t0 = (float)step * h;

            for (int s = 0; s < 6; s++) {
                dense256<Dd + 1, true>(W1, b1, sZ,  sH1, lane, g, r0);
                __syncthreads();
                dense256<Hh,     true>(W2, b2, sH1, sH2, lane, g, r0);
                __syncthreads();

                float cf[5], cfr, tnext;
                bool writeY = (s == 5);
                if (s < 5) {
#pragma unroll
                    for (int l = 0; l < 5; l++) cf[l] = h * DP_A[s+1][l];
                    cfr = h * DP_A[s+1][s];
                    tnext = t0 + DP_C[s+1] * h;
                } else {
#pragma unroll
                    for (int l = 0; l < 5; l++) cf[l] = h * DP_B[l];
                    cfr = h * DP_B[5];
                    tnext = (step == NSTEPS - 1) ? 0.0f : (float)(step + 1) * h;
                }
                dense64_fused(W3, b3, sH2, sK, sY, sZ,
                              cf, cfr, s, tnext, writeY, lane, r0d);
                __syncthreads();
            }
        }
    }

    for (int i = tid; i < MROWS * Dd; i += NT) {
        int r = i >> 6, d = i & 63;
        out[(rbase + r) * Dd + d] = sY[d * STRY + r];
    }
}

extern "C" void kernel_launch(void* const* d_in, const int* in_sizes, int n_in,
                              void* d_out, int out_size)
{
    (void)in_sizes; (void)n_in; (void)out_size;
    const float* x = (const float*)d_in[0];

    FfjordParams P;
    P.W1[0] = (const float*)d_in[1];  P.b1[0] = (const float*)d_in[2];
    P.W2[0] = (const float*)d_in[3];  P.b2[0] = (const float*)d_in[4];
    P.W3[0] = (const float*)d_in[5];  P.b3[0] = (const float*)d_in[6];
    P.W1[1] = (const float*)d_in[7];  P.b1[1] = (const float*)d_in[8];
    P.W2[1] = (const float*)d_in[9];  P.b2[1] = (const float*)d_in[10];
    P.W3[1] = (const float*)d_in[11]; P.b3[1] = (const float*)d_in[12];

    static_assert(SM_BYTES <= 100 * 1024, "smem budget (2 CTAs/SM)");
    cudaFuncSetAttribute(ffjord_kernel, cudaFuncAttributeMaxDynamicSharedMemorySize, SM_BYTES);

    ffjord_kernel<<<NCTAS, NT, SM_BYTES>>>(x, (float*)d_out, P);
}